// round 3
// baseline (speedup 1.0000x reference)
#include <cuda_runtime.h>
#include <cuda_fp16.h>

#define NE   1024
#define NIN  64
#define HID  128
#define NOUT 64

// Scratch (__device__ globals per allocation-free rule)
__device__ float  g_A [NE * HID];   // fp32 A = x@W1a + b1 (for self-term)
__device__ float  g_B [NE * HID];   // fp32 B = x@W1b      (for self-term)
__device__ __half g_Ah[NE * HID];   // f16 A, [i][h]
__device__ __half g_Bt[HID * NE];   // f16 B, transposed [h][perm(p)]
__device__ float  g_S [NE * HID];   // sum over ALL p of tanh(A_i + B_p)

__device__ __forceinline__ float tanh_fast(float x) {
    float y;
    asm("tanh.approx.f32 %0, %1;" : "=f"(y) : "f"(x));
    return y;
}

__device__ __forceinline__ unsigned tanh2(unsigned x) {
    unsigned y;
    asm("tanh.approx.f16x2 %0, %1;" : "=r"(y) : "r"(x));
    return y;
}

__device__ __forceinline__ unsigned hadd2u(__half2 a, __half2 b) {
    __half2 r = __hadd2(a, b);
    return *reinterpret_cast<unsigned*>(&r);
}

// m16n8k16 f16 mma, f32 accum. D = A*B + D.
__device__ __forceinline__ void mma16816(float& c0, float& c1, float& c2, float& c3,
                                         unsigned a0, unsigned a1, unsigned a2, unsigned a3,
                                         unsigned b0, unsigned b1) {
    asm volatile(
        "mma.sync.aligned.m16n8k16.row.col.f32.f16.f16.f32 "
        "{%0,%1,%2,%3}, {%4,%5,%6,%7}, {%8,%9}, {%0,%1,%2,%3};"
        : "+f"(c0), "+f"(c1), "+f"(c2), "+f"(c3)
        : "r"(a0), "r"(a1), "r"(a2), "r"(a3), "r"(b0), "r"(b1));
}

// Position of partner-column m (0..15) in the permuted 16-block so that lane
// q = lane&3 reads its fragment k-cols {2q,2q+1,2q+8,2q+9} as one 8-byte LDS.
__device__ __forceinline__ int permpos(int m) {
    return ((m & 7) >> 1) * 4 + ((m >> 3) & 1) * 2 + (m & 1);
}

// ---------------------------------------------------------------------------
// K1: projection, 8 rows per block (amortize W1 reads 8x).
// grid = 128, block = 128 (thread = hidden unit h)
// ---------------------------------------------------------------------------
__global__ void __launch_bounds__(128) k_proj(const float* __restrict__ x,
                                              const float* __restrict__ W1,
                                              const float* __restrict__ b1) {
    const int h  = threadIdx.x;
    const int i0 = blockIdx.x * 8;

    __shared__ float sx[8][NIN];
#pragma unroll
    for (int k = 0; k < 4; k++) {
        const int lin = k * 128 + h;            // 0..511
        sx[lin >> 6][lin & 63] = x[i0 * NIN + lin];
    }
    __syncthreads();

    const float b1v = b1[h];
    float a[8], b[8];
#pragma unroll
    for (int r = 0; r < 8; r++) { a[r] = b1v; b[r] = 0.f; }

#pragma unroll
    for (int f = 0; f < NIN; f++) {
        const float w1a = W1[f * HID + h];
        const float w1b = W1[(NIN + f) * HID + h];
#pragma unroll
        for (int r = 0; r < 8; r++) {
            a[r] = fmaf(sx[r][f], w1a, a[r]);
            b[r] = fmaf(sx[r][f], w1b, b[r]);
        }
    }

#pragma unroll
    for (int r = 0; r < 8; r++) {
        const int i   = i0 + r;
        const int idx = i * HID + h;
        g_A[idx]  = a[r];
        g_B[idx]  = b[r];
        g_Ah[idx] = __float2half(a[r]);
        const int pp = (i & ~15) | permpos(i & 15);
        g_Bt[h * NE + pp] = __float2half(b[r]);
    }
}

// ---------------------------------------------------------------------------
// K2: pairwise tanh sums via f16x2 MUFU + HMMA(ones) accumulation.
// Warp = (16-row i-block, hidden h); block = 4 warps = 4 consecutive h.
// grid = 64 iblk * 32 hgroups = 2048, block = 128.
// ---------------------------------------------------------------------------
__global__ void __launch_bounds__(128, 8) k_pair(void) {
    const int tid  = threadIdx.x;
    const int w    = tid >> 5;
    const int lane = tid & 31;
    const int hg   = blockIdx.x & 31;
    const int iblk = blockIdx.x >> 5;
    const int h0   = hg * 4;
    const int h    = h0 + w;

    __shared__ __half sB[4][NE];   // 8 KB: B rows h0..h0+3, permuted along p

    // cooperative coalesced load: 8 KB = 512 uint4
    {
        const uint4* src = reinterpret_cast<const uint4*>(g_Bt + h0 * NE);
        uint4*       dst = reinterpret_cast<uint4*>(&sB[0][0]);
#pragma unroll
        for (int k = 0; k < 4; k++) dst[k * 128 + tid] = src[k * 128 + tid];
    }

    const int g = lane >> 2;   // row group 0..7
    const int q = lane & 3;    // k-col group

    const __half2 ag  = __half2half2(g_Ah[(iblk * 16 + g)     * HID + h]);
    const __half2 ag8 = __half2half2(g_Ah[(iblk * 16 + g + 8) * HID + h]);
    __syncthreads();

    float c0a = 0.f, c1a = 0.f, c2a = 0.f, c3a = 0.f;   // even kb accum
    float c0b = 0.f, c1b = 0.f, c2b = 0.f, c3b = 0.f;   // odd  kb accum
    const unsigned ONES = 0x3C003C00u;

    const __half2* rowB = reinterpret_cast<const __half2*>(&sB[w][0]);

#pragma unroll 8
    for (int kb = 0; kb < 64; kb++) {
        // lane's 4 fragment k-values: 8 bytes at permuted offset
        const uint2 bv = *reinterpret_cast<const uint2*>(rowB + kb * 8 + q * 2);
        const __half2 blo = *reinterpret_cast<const __half2*>(&bv.x);
        const __half2 bhi = *reinterpret_cast<const __half2*>(&bv.y);

        const unsigned t0 = tanh2(hadd2u(ag,  blo));   // (g,    k 2q..2q+1)
        const unsigned t1 = tanh2(hadd2u(ag8, blo));   // (g+8,  k 2q..2q+1)
        const unsigned t2 = tanh2(hadd2u(ag,  bhi));   // (g,    k 2q+8..+9)
        const unsigned t3 = tanh2(hadd2u(ag8, bhi));   // (g+8,  k 2q+8..+9)

        if (kb & 1) mma16816(c0b, c1b, c2b, c3b, t0, t1, t2, t3, ONES, ONES);
        else        mma16816(c0a, c1a, c2a, c3a, t0, t1, t2, t3, ONES, ONES);
    }

    // C fragment: c0 = row g (any n-col; all equal since B=ones), c2 = row g+8
    if (q == 0) {
        g_S[(iblk * 16 + g)     * HID + h] = c0a + c0b;
        g_S[(iblk * 16 + g + 8) * HID + h] = c2a + c2b;
    }
}

// ---------------------------------------------------------------------------
// K3: subtract fp32 self-term, scale, fused W2 epilogue.
// grid = 256, block = 128.
// ---------------------------------------------------------------------------
__global__ void __launch_bounds__(128) k_combine(const float* __restrict__ W2,
                                                 const float* __restrict__ b2,
                                                 float* __restrict__ out) {
    const int h  = threadIdx.x;
    const int r0 = blockIdx.x * 4;
    const float inv = 1.0f / (float)(NE - 1);

    __shared__ float sacc[4][HID];
#pragma unroll
    for (int r = 0; r < 4; r++) {
        const int idx = (r0 + r) * HID + h;
        const float s = g_S[idx] - tanh_fast(g_A[idx] + g_B[idx]);  // exclude p==i
        sacc[r][h] = s * inv;
    }
    __syncthreads();

#pragma unroll
    for (int k = 0; k < 2; k++) {
        const int idx = k * HID + h;          // 0..255
        const int r   = idx >> 6;
        const int o   = idx & (NOUT - 1);
        float acc = b2[o];
#pragma unroll
        for (int hh = 0; hh < HID; hh++)
            acc = fmaf(sacc[r][hh], W2[hh * NOUT + o], acc);
        out[(r0 + r) * NOUT + o] = acc;
    }
}

// ---------------------------------------------------------------------------
extern "C" void kernel_launch(void* const* d_in, const int* in_sizes, int n_in,
                              void* d_out, int out_size) {
    const float* x  = (const float*)d_in[0];
    const float* W1 = (const float*)d_in[1];
    const float* b1 = (const float*)d_in[2];
    const float* W2 = (const float*)d_in[3];
    const float* b2 = (const float*)d_in[4];
    float* out = (float*)d_out;

    k_proj<<<128, 128>>>(x, W1, b1);
    k_pair<<<2048, 128>>>();
    k_combine<<<256, 128>>>(W2, b2, out);
}

// round 5
// speedup vs baseline: 1.2109x; 1.2109x over previous
#include <cuda_runtime.h>
#include <math.h>

#define NE   1024
#define NIN  64
#define HID  128
#define NOUT 64
#define ND   48      // Chebyshev nodes / coefficients per hidden unit

// Scratch (__device__ globals per allocation-free rule)
__device__ float g_A [NE * HID];    // A = x@W1a + b1,   [i][h]
__device__ float g_B [NE * HID];    // B = x@W1b,        [i][h]
__device__ float g_C [ND * HID];    // Chebyshev coeffs, [k][h]
__device__ float g_CR[2 * HID];     // center [h], halfwidth [128+h]

__device__ __forceinline__ float tanh_fast(float x) {
    float y;
    asm("tanh.approx.f32 %0, %1;" : "=f"(y) : "f"(x));
    return y;
}

// ---------------------------------------------------------------------------
// K1: projection. 512 blocks x 2 rows, thread = hidden unit h.
// ---------------------------------------------------------------------------
__global__ void __launch_bounds__(128) k_proj(const float* __restrict__ x,
                                              const float* __restrict__ W1,
                                              const float* __restrict__ bias1) {
    const int h  = threadIdx.x;
    const int i0 = blockIdx.x * 2;

    __shared__ float sx[2][NIN];
    sx[h >> 6][h & 63] = x[i0 * NIN + h];   // 128 threads load 2 rows
    __syncthreads();

    const float bv = bias1[h];
    float a0 = bv, a1 = bv, s0 = 0.f, s1 = 0.f;
#pragma unroll
    for (int f = 0; f < NIN; f++) {
        const float w1a = W1[f * HID + h];
        const float w1b = W1[(NIN + f) * HID + h];
        a0 = fmaf(sx[0][f], w1a, a0);
        a1 = fmaf(sx[1][f], w1a, a1);
        s0 = fmaf(sx[0][f], w1b, s0);
        s1 = fmaf(sx[1][f], w1b, s1);
    }
    g_A[(i0 + 0) * HID + h] = a0;
    g_A[(i0 + 1) * HID + h] = a1;
    g_B[(i0 + 0) * HID + h] = s0;
    g_B[(i0 + 1) * HID + h] = s1;
}

// ---------------------------------------------------------------------------
// K2: per-h Chebyshev model of F_h(a) = sum_p tanh(a + B[p][h]).
// grid = HID blocks (block = h), 128 threads.
// ---------------------------------------------------------------------------
__global__ void __launch_bounds__(128) k_cheb(void) {
    const int h    = blockIdx.x;
    const int t    = threadIdx.x;
    const int lane = t & 31;
    const int w    = t >> 5;

    __shared__ float s_nodes[ND];
    __shared__ float s_part[ND * 4];
    __shared__ float s_F[ND];
    __shared__ float s_mm[8];      // 4 warps x {min,max}
    __shared__ float s_cr[2];

    // ---- 1) per-h min/max of A ----
    float amin =  1e30f, amax = -1e30f;
#pragma unroll
    for (int m = 0; m < 8; m++) {
        const float v = g_A[(t + 128 * m) * HID + h];
        amin = fminf(amin, v);
        amax = fmaxf(amax, v);
    }
#pragma unroll
    for (int d = 16; d > 0; d >>= 1) {
        amin = fminf(amin, __shfl_xor_sync(0xffffffffu, amin, d));
        amax = fmaxf(amax, __shfl_xor_sync(0xffffffffu, amax, d));
    }
    if (lane == 0) { s_mm[w] = amin; s_mm[4 + w] = amax; }
    __syncthreads();
    if (t == 0) {
        float mn = fminf(fminf(s_mm[0], s_mm[1]), fminf(s_mm[2], s_mm[3]));
        float mx = fmaxf(fmaxf(s_mm[4], s_mm[5]), fmaxf(s_mm[6], s_mm[7]));
        const float c = 0.5f * (mn + mx);
        const float r = fmaxf(0.5f * (mx - mn), 1e-4f);
        s_cr[0] = c; s_cr[1] = r;
        g_CR[h]       = c;
        g_CR[HID + h] = r;
    }
    __syncthreads();

    // ---- 2) Chebyshev nodes a_j = c + r*cos(pi*(j+0.5)/ND) ----
    if (t < ND) {
        const float xj = cospif((t + 0.5f) / (float)ND);
        s_nodes[t] = fmaf(s_cr[1], xj, s_cr[0]);
    }
    __syncthreads();

    // ---- 3) F at nodes: each thread sums its 8 partners over all nodes ----
    float part[ND];
#pragma unroll
    for (int j = 0; j < ND; j++) part[j] = 0.f;

#pragma unroll
    for (int m = 0; m < 8; m++) {
        const float bv = g_B[(t + 128 * m) * HID + h];
#pragma unroll
        for (int j = 0; j < ND; j++)
            part[j] += tanh_fast(s_nodes[j] + bv);
    }

    // ---- 4) reduce over 128 threads ----
#pragma unroll
    for (int j = 0; j < ND; j++) {
        float v = part[j];
#pragma unroll
        for (int d = 16; d > 0; d >>= 1)
            v += __shfl_xor_sync(0xffffffffu, v, d);
        if (lane == 0) s_part[j * 4 + w] = v;
    }
    __syncthreads();
    if (t < ND)
        s_F[t] = s_part[t * 4] + s_part[t * 4 + 1] + s_part[t * 4 + 2] + s_part[t * 4 + 3];
    __syncthreads();

    // ---- 5) DCT-II -> Chebyshev coefficients, stored [k][h] ----
    if (t < ND) {
        const int k = t;
        float sum = 0.f;
#pragma unroll 8
        for (int j = 0; j < ND; j++)
            sum = fmaf(s_F[j], cospif((float)k * (j + 0.5f) / (float)ND), sum);
        const float scale = (k == 0) ? (1.0f / ND) : (2.0f / ND);
        g_C[k * HID + h] = sum * scale;
    }
}

// ---------------------------------------------------------------------------
// K3: Clenshaw eval + self-term + mean + fused W2 epilogue.
// grid = NE/4 = 256 blocks, 128 threads (thread = h, 4 rows per block).
// ---------------------------------------------------------------------------
__global__ void __launch_bounds__(128) k_evalout(const float* __restrict__ W2,
                                                 const float* __restrict__ b2,
                                                 float* __restrict__ out) {
    const int h  = threadIdx.x;
    const int r0 = blockIdx.x * 4;

    const float c    = g_CR[h];
    const float rinv = 1.0f / g_CR[HID + h];

    float tt[4], bb1[4], bb2[4];
#pragma unroll
    for (int rr = 0; rr < 4; rr++) {
        tt[rr]  = (g_A[(r0 + rr) * HID + h] - c) * rinv;   // in [-1,1]
        bb1[rr] = 0.f;
        bb2[rr] = 0.f;
    }

    // Clenshaw: for k = ND-1..1: b_k = a_k + 2t*b_{k+1} - b_{k+2}
#pragma unroll
    for (int k = ND - 1; k >= 1; k--) {
        const float ak = g_C[k * HID + h];
#pragma unroll
        for (int rr = 0; rr < 4; rr++) {
            const float bn = fmaf(2.0f * tt[rr], bb1[rr], ak - bb2[rr]);
            bb2[rr] = bb1[rr];
            bb1[rr] = bn;
        }
    }
    const float a0  = g_C[h];
    const float inv = 1.0f / (float)(NE - 1);

    __shared__ float sacc[4][HID];
#pragma unroll
    for (int rr = 0; rr < 4; rr++) {
        const int idx = (r0 + rr) * HID + h;
        float F = fmaf(tt[rr], bb1[rr], a0 - bb2[rr]);     // sum over ALL p
        F -= tanh_fast(g_A[idx] + g_B[idx]);               // exclude p == i
        sacc[rr][h] = F * inv;
    }
    __syncthreads();

    // W2 epilogue: 4*NOUT = 256 outputs, 128 threads -> 2 each.
#pragma unroll
    for (int k = 0; k < 2; k++) {
        const int idx = k * HID + h;
        const int rr  = idx >> 6;
        const int o   = idx & (NOUT - 1);
        float acc = b2[o];
#pragma unroll
        for (int hh = 0; hh < HID; hh++)
            acc = fmaf(sacc[rr][hh], W2[hh * NOUT + o], acc);
        out[(r0 + rr) * NOUT + o] = acc;
    }
}

// ---------------------------------------------------------------------------
extern "C" void kernel_launch(void* const* d_in, const int* in_sizes, int n_in,
                              void* d_out, int out_size) {
    const float* x  = (const float*)d_in[0];
    const float* W1 = (const float*)d_in[1];
    const float* b1 = (const float*)d_in[2];
    const float* W2 = (const float*)d_in[3];
    const float* b2 = (const float*)d_in[4];
    float* out = (float*)d_out;

    k_proj<<<NE / 2, HID>>>(x, W1, b1);
    k_cheb<<<HID, 128>>>();
    k_evalout<<<NE / 4, HID>>>(W2, b2, out);
}

// round 10
// speedup vs baseline: 2.3268x; 1.9216x over previous
#include <cuda_runtime.h>
#include <math.h>

#define NE   1024
#define NIN  64
#define HID  128
#define NOUT 64
#define ND   48      // Chebyshev nodes / coefficients per hidden unit
#define PS   8       // partner splits in k_chebF

// Scratch (__device__ globals per allocation-free rule)
__device__ float g_A  [NE * HID];   // A = x@W1a + b1, [i][h]
__device__ float g_B  [NE * HID];   // B = x@W1b,      [i][h]
__device__ float g_Bt [HID * NE];   // B transposed,   [h][i]
__device__ float g_F  [ND * HID];   // F_h at nodes,   [j][h] (atomicAdd target)
__device__ float g_C  [ND * HID];   // Chebyshev coeffs [k][h]
__device__ int   g_MaxI[HID];       // per-h max|A| as ordered int (atomicMax)

__device__ __forceinline__ float tanh_fast(float x) {
    float y;
    asm("tanh.approx.f32 %0, %1;" : "=f"(y) : "f"(x));
    return y;
}

// ---------------------------------------------------------------------------
// K1: projection. grid 256 x block 256 = (f-half, h), 4 rows per block.
// Emits A,B ([i][h]), Bt ([h][i]), per-h atomicMax|A|; zeros g_F (block 0).
// ---------------------------------------------------------------------------
__global__ void __launch_bounds__(256) k_proj(const float* __restrict__ x,
                                              const float* __restrict__ W1,
                                              const float* __restrict__ bias1) {
    const int tid = threadIdx.x;
    const int fh  = tid >> 7;        // which half of f-range
    const int h   = tid & 127;
    const int i0  = blockIdx.x * 4;

    // zero the F accumulator once per launch (atomicAdd target in k_chebF)
    if (blockIdx.x == 0)
        for (int k = tid; k < ND * HID; k += 256) g_F[k] = 0.f;

    __shared__ float sx[4][NIN];
    sx[tid >> 6][tid & 63] = x[i0 * NIN + tid];
    __syncthreads();

    float a[4], b[4];
    const float binit = (fh == 0) ? bias1[h] : 0.f;
#pragma unroll
    for (int r = 0; r < 4; r++) { a[r] = binit; b[r] = 0.f; }

    const int f0 = fh * 32;
#pragma unroll
    for (int ff = 0; ff < 32; ff++) {
        const int f = f0 + ff;
        const float w1a = W1[f * HID + h];
        const float w1b = W1[(NIN + f) * HID + h];
#pragma unroll
        for (int r = 0; r < 4; r++) {
            a[r] = fmaf(sx[r][f], w1a, a[r]);
            b[r] = fmaf(sx[r][f], w1b, b[r]);
        }
    }

    __shared__ float s_ab[8][HID];
    if (fh == 1) {
#pragma unroll
        for (int r = 0; r < 4; r++) {
            s_ab[r][h]     = a[r];
            s_ab[4 + r][h] = b[r];
        }
    }
    __syncthreads();
    if (fh == 0) {
        float m = 0.f;
#pragma unroll
        for (int r = 0; r < 4; r++) {
            const float av = a[r] + s_ab[r][h];
            const float bv = b[r] + s_ab[4 + r][h];
            const int i = i0 + r;
            g_A[i * HID + h] = av;
            g_B[i * HID + h] = bv;
            g_Bt[h * NE + i] = bv;
            m = fmaxf(m, fabsf(av));
        }
        atomicMax(&g_MaxI[h], __float_as_int(m));   // m>=0: int order == float order
    }
}

// ---------------------------------------------------------------------------
// K2: F_h(node_j) = sum_p tanh(node_j + B[p][h]), partial over 128 partners.
// grid = 128 h * PS = 1024 blocks, 128 threads. Warp w owns nodes [12w,12w+12).
// ---------------------------------------------------------------------------
__global__ void __launch_bounds__(128, 8) k_chebF(void) {
    const int bx   = blockIdx.x;
    const int h    = bx & 127;
    const int ps   = bx >> 7;
    const int t    = threadIdx.x;
    const int w    = t >> 5;
    const int lane = t & 31;

    const float r = fmaxf(__int_as_float(g_MaxI[h]), 1e-4f);

    float nodes[12];
#pragma unroll
    for (int jj = 0; jj < 12; jj++)
        nodes[jj] = r * cospif((w * 12 + jj + 0.5f) * (1.0f / ND));

    float part[12];
#pragma unroll
    for (int jj = 0; jj < 12; jj++) part[jj] = 0.f;

    const float* __restrict__ rowB = g_Bt + h * NE + ps * 128;
#pragma unroll
    for (int m = 0; m < 4; m++) {
        const float bv = rowB[m * 32 + lane];
#pragma unroll
        for (int jj = 0; jj < 12; jj++)
            part[jj] += tanh_fast(nodes[jj] + bv);
    }

#pragma unroll
    for (int jj = 0; jj < 12; jj++) {
#pragma unroll
        for (int d = 16; d; d >>= 1)
            part[jj] += __shfl_xor_sync(0xffffffffu, part[jj], d);
        if (lane == jj)
            atomicAdd(&g_F[(w * 12 + jj) * HID + h], part[jj]);
    }
}

// ---------------------------------------------------------------------------
// K3: DCT-II -> Chebyshev coefficients. grid = ND blocks (k), 128 threads (h).
// ---------------------------------------------------------------------------
__global__ void __launch_bounds__(128) k_chebC(void) {
    const int k = blockIdx.x;
    const int h = threadIdx.x;
    float sum = 0.f;
#pragma unroll 8
    for (int j = 0; j < ND; j++)
        sum = fmaf(g_F[j * HID + h], cospif((float)k * (j + 0.5f) * (1.0f / ND)), sum);
    g_C[k * HID + h] = sum * ((k == 0) ? (1.0f / ND) : (2.0f / ND));
}

// ---------------------------------------------------------------------------
// K4: Clenshaw eval + self-term + mean + fused W2 epilogue.
// grid = NE/4 = 256 blocks, 128 threads (thread = h, 4 rows per block).
// ---------------------------------------------------------------------------
__global__ void __launch_bounds__(128) k_evalout(const float* __restrict__ W2,
                                                 const float* __restrict__ b2,
                                                 float* __restrict__ out) {
    const int h  = threadIdx.x;
    const int r0 = blockIdx.x * 4;

    const float rinv = 1.0f / fmaxf(__int_as_float(g_MaxI[h]), 1e-4f);

    float tt[4], bb1[4], bb2[4];
#pragma unroll
    for (int rr = 0; rr < 4; rr++) {
        tt[rr]  = g_A[(r0 + rr) * HID + h] * rinv;   // in [-1,1] (range symmetric)
        bb1[rr] = 0.f;
        bb2[rr] = 0.f;
    }

#pragma unroll
    for (int k = ND - 1; k >= 1; k--) {
        const float ak = g_C[k * HID + h];
#pragma unroll
        for (int rr = 0; rr < 4; rr++) {
            const float bn = fmaf(2.0f * tt[rr], bb1[rr], ak - bb2[rr]);
            bb2[rr] = bb1[rr];
            bb1[rr] = bn;
        }
    }
    const float a0  = g_C[h];
    const float inv = 1.0f / (float)(NE - 1);

    __shared__ float sacc[4][HID];
#pragma unroll
    for (int rr = 0; rr < 4; rr++) {
        const int idx = (r0 + rr) * HID + h;
        float F = fmaf(tt[rr], bb1[rr], a0 - bb2[rr]);     // sum over ALL p
        F -= tanh_fast(g_A[idx] + g_B[idx]);               // exclude p == i
        sacc[rr][h] = F * inv;
    }
    __syncthreads();

#pragma unroll
    for (int k = 0; k < 2; k++) {
        const int idx = k * HID + h;
        const int rr  = idx >> 6;
        const int o   = idx & (NOUT - 1);
        float acc = b2[o];
#pragma unroll
        for (int hh = 0; hh < HID; hh++)
            acc = fmaf(sacc[rr][hh], W2[hh * NOUT + o], acc);
        out[(r0 + rr) * NOUT + o] = acc;
    }
}

// ---------------------------------------------------------------------------
extern "C" void kernel_launch(void* const* d_in, const int* in_sizes, int n_in,
                              void* d_out, int out_size) {
    const float* x  = (const float*)d_in[0];
    const float* W1 = (const float*)d_in[1];
    const float* b1 = (const float*)d_in[2];
    const float* W2 = (const float*)d_in[3];
    const float* b2 = (const float*)d_in[4];
    float* out = (float*)d_out;

    k_proj<<<NE / 4, 256>>>(x, W1, b1);
    k_chebF<<<HID * PS, 128>>>();
    k_chebC<<<ND, 128>>>();
    k_evalout<<<NE / 4, 128>>>(W2, b2, out);
}